// round 10
// baseline (speedup 1.0000x reference)
#include <cuda_runtime.h>
#include <cstdint>
#include <math.h>

#define T_TOK 2048
#define DDIM  1024
#define NEXP  64
#define TOPK  8
#define FDIM  768
#define CAP   512

// -------------------- device scratch --------------------
__device__ int   g_cnt[NEXP];
__device__ int   g_slot_tok[NEXP * CAP];
__device__ float g_slot_w[NEXP * CAP];
__device__ float g_H[(size_t)NEXP * CAP * FDIM];        // ~100.7 MB
__device__ float g_shared_h[(size_t)T_TOK * FDIM];      // ~6.3 MB

// -------------------- helpers --------------------
__device__ __forceinline__ uint32_t f2tf32(float x) {
    uint32_t r;
    asm("cvt.rna.tf32.f32 %0, %1;" : "=r"(r) : "f"(x));
    return r;
}

__device__ __forceinline__ void cvt_store4r(float* dst, float4 v) {
    uint4 o;
    o.x = f2tf32(v.x); o.y = f2tf32(v.y); o.z = f2tf32(v.z); o.w = f2tf32(v.w);
    *reinterpret_cast<uint4*>(dst) = o;
}

__device__ __forceinline__ void mma8(float c[4], const uint32_t a[4],
                                     uint32_t b0, uint32_t b1) {
    asm volatile(
        "mma.sync.aligned.m16n8k8.row.col.f32.tf32.tf32.f32 "
        "{%0,%1,%2,%3},{%4,%5,%6,%7},{%8,%9},{%0,%1,%2,%3};\n"
        : "+f"(c[0]), "+f"(c[1]), "+f"(c[2]), "+f"(c[3])
        : "r"(a[0]), "r"(a[1]), "r"(a[2]), "r"(a[3]), "r"(b0), "r"(b1));
}

// -------------------- counters / output reset --------------------
__global__ void zero_cnt_kernel() {
    if (threadIdx.x < NEXP) g_cnt[threadIdx.x] = 0;
}
__global__ void zero_out_kernel(float4* out) {
    out[blockIdx.x * 256 + threadIdx.x] = make_float4(0.f, 0.f, 0.f, 0.f);
}

// -------------------- router --------------------
__global__ __launch_bounds__(256)
void router_kernel(const float* __restrict__ X, const float* __restrict__ RW) {
    __shared__ float xs[32][68];
    __shared__ float rws[64][68];
    __shared__ float probs[32][65];

    const int tid = threadIdx.x;
    const int t0  = blockIdx.x * 32;
    const int t   = tid >> 3;
    const int el  = tid & 7;

    float acc[8] = {0.f,0.f,0.f,0.f,0.f,0.f,0.f,0.f};

    for (int kc = 0; kc < DDIM; kc += 64) {
        #pragma unroll
        for (int i = 0; i < 2; i++) {
            int idx = tid + i * 256;
            int row = idx >> 4, c4 = idx & 15;
            *reinterpret_cast<float4*>(&xs[row][c4 * 4]) =
                *reinterpret_cast<const float4*>(X + (size_t)(t0 + row) * DDIM + kc + c4 * 4);
        }
        #pragma unroll
        for (int i = 0; i < 4; i++) {
            int idx = tid + i * 256;
            int row = idx >> 4, c4 = idx & 15;
            *reinterpret_cast<float4*>(&rws[row][c4 * 4]) =
                *reinterpret_cast<const float4*>(RW + (size_t)row * DDIM + kc + c4 * 4);
        }
        __syncthreads();
        for (int k = 0; k < 64; k++) {
            float xv = xs[t][k];
            #pragma unroll
            for (int j = 0; j < 8; j++) acc[j] += xv * rws[el + 8 * j][k];
        }
        __syncthreads();
    }

    float mx = acc[0];
    #pragma unroll
    for (int j = 1; j < 8; j++) mx = fmaxf(mx, acc[j]);
    #pragma unroll
    for (int m = 1; m < 8; m <<= 1) mx = fmaxf(mx, __shfl_xor_sync(0xffffffffu, mx, m));
    float p[8], s = 0.f;
    #pragma unroll
    for (int j = 0; j < 8; j++) { p[j] = expf(acc[j] - mx); s += p[j]; }
    #pragma unroll
    for (int m = 1; m < 8; m <<= 1) s += __shfl_xor_sync(0xffffffffu, s, m);
    float inv = 1.f / s;
    #pragma unroll
    for (int j = 0; j < 8; j++) probs[t][el + 8 * j] = p[j] * inv;
    __syncthreads();

    if (tid < 32) {
        const int token = t0 + tid;
        float tw[TOPK]; int te[TOPK];
        float psum = 0.f;
        #pragma unroll
        for (int k = 0; k < TOPK; k++) {
            float best = -1.f; int be = 0;
            for (int e2 = 0; e2 < NEXP; e2++) {
                float v = probs[tid][e2];
                if (v > best) { best = v; be = e2; }
            }
            probs[tid][be] = -2.f;
            tw[k] = best; te[k] = be; psum += best;
        }
        float invp = 1.f / psum;
        #pragma unroll
        for (int k = 0; k < TOPK; k++) {
            int pos = atomicAdd(&g_cnt[te[k]], 1);
            if (pos < CAP) {
                g_slot_tok[te[k] * CAP + pos] = token;
                g_slot_w[te[k] * CAP + pos]   = tw[k] * invp;
            }
        }
    }
}

// ==================== fused gate/up GEMM + SiLU ====================
// BM=64, BN=128, BK=32, 256 threads (8 warps 2m x 4n of 32x32), 2 CTAs/SM.
// Buffer words: A 64*36=2304, Bg 32*136=4352, Bu 4352 => 11008; x2 buffers.
// Split prefetch: LDG(A,Bhalf1) -> ks01 -> STS + LDG(Bhalf2) -> ks23 -> STS -> sync
__global__ __launch_bounds__(256, 2)
void gateup_kernel(const float* __restrict__ X, const float* __restrict__ WG,
                   const float* __restrict__ WU, const float* __restrict__ WSG) {
    extern __shared__ float smem[];
    float* bufs = smem;
    int* s_tok = (int*)(smem + 2 * 11008);

    const int tid = threadIdx.x;
    const int z   = blockIdx.z;
    const bool expert = (z < NEXP);
    const int e  = expert ? z : 0;
    const int ne = expert ? min(g_cnt[e], CAP) : T_TOK;
    const int m0 = expert ? blockIdx.y * 64 : (((z - NEXP) * 8 + blockIdx.y) * 64);
    if (m0 >= ne) return;
    const int n0 = blockIdx.x * 128;
    const int ldb = expert ? FDIM : 2 * FDIM;

    const float* Bg = expert ? (WG + (size_t)e * DDIM * FDIM) : WSG;
    const float* Bu = expert ? (WU + (size_t)e * DDIM * FDIM) : (WSG + FDIM);

    if (expert) {
        if (tid < 64) {
            int m = m0 + tid;
            s_tok[tid] = (m < ne) ? g_slot_tok[e * CAP + m] : 0;
        }
        __syncthreads();
    }

    // producer coords: A 2 float4/thread; B 4 float4/thread/matrix
    const float* rpA[2];
    int arow[2], ac4[2], brow[4], bc4[4];
    #pragma unroll
    for (int i = 0; i < 2; i++) {
        int idx = tid + i * 256;
        arow[i] = idx >> 3; ac4[i] = idx & 7;
        rpA[i] = expert ? (X + (size_t)s_tok[arow[i]] * DDIM)
                        : (X + (size_t)(m0 + arow[i]) * DDIM);
    }
    #pragma unroll
    for (int i = 0; i < 4; i++) {
        int idx = tid + i * 256;
        brow[i] = idx >> 5; bc4[i] = idx & 31;
    }

    const int lane = tid & 31, warp = tid >> 5;
    const int wm = (warp >> 2) * 32, wn = (warp & 3) * 32;
    const int g = lane >> 2, tig = lane & 3;

    float cG[2][4][4] = {};
    float cU[2][4][4] = {};

    float4 hA[2], hBg1[2], hBu1[2], hBg2[2], hBu2[2];

    // ---- prologue: tile 0 fully ----
    #pragma unroll
    for (int i = 0; i < 2; i++) {
        hA[i] = *reinterpret_cast<const float4*>(rpA[i] + ac4[i] * 4);
        size_t go1 = (size_t)brow[i] * ldb + n0 + bc4[i] * 4;
        size_t go2 = (size_t)brow[i + 2] * ldb + n0 + bc4[i + 2] * 4;
        hBg1[i] = *reinterpret_cast<const float4*>(Bg + go1);
        hBu1[i] = *reinterpret_cast<const float4*>(Bu + go1);
        hBg2[i] = *reinterpret_cast<const float4*>(Bg + go2);
        hBu2[i] = *reinterpret_cast<const float4*>(Bu + go2);
    }
    {
        float* sA  = bufs;
        float* sBg = sA + 2304;
        float* sBu = sBg + 4352;
        #pragma unroll
        for (int i = 0; i < 2; i++) {
            cvt_store4r(&sA[arow[i] * 36 + ac4[i] * 4], hA[i]);
            cvt_store4r(&sBg[brow[i] * 136 + bc4[i] * 4], hBg1[i]);
            cvt_store4r(&sBu[brow[i] * 136 + bc4[i] * 4], hBu1[i]);
            cvt_store4r(&sBg[brow[i + 2] * 136 + bc4[i + 2] * 4], hBg2[i]);
            cvt_store4r(&sBu[brow[i + 2] * 136 + bc4[i + 2] * 4], hBu2[i]);
        }
    }
    __syncthreads();

    const int NK = DDIM / 32;
    for (int kt = 0; kt < NK; kt++) {
        const bool more = (kt + 1 < NK);
        const int k1 = (kt + 1) * 32;
        const uint32_t* uA  = (const uint32_t*)(bufs + (kt & 1) * 11008);
        const uint32_t* uBg = uA + 2304;
        const uint32_t* uBu = uBg + 4352;
        float* nA  = bufs + ((kt + 1) & 1) * 11008;
        float* nBg = nA + 2304;
        float* nBu = nBg + 4352;

        // prefetch A + B first half (k rows 0..15) of next tile
        if (more) {
            #pragma unroll
            for (int i = 0; i < 2; i++) {
                hA[i] = *reinterpret_cast<const float4*>(rpA[i] + k1 + ac4[i] * 4);
                size_t go = (size_t)(k1 + brow[i]) * ldb + n0 + bc4[i] * 4;
                hBg1[i] = *reinterpret_cast<const float4*>(Bg + go);
                hBu1[i] = *reinterpret_cast<const float4*>(Bu + go);
            }
        }

        // compute ks = 0,1
        #pragma unroll
        for (int ks = 0; ks < 2; ks++) {
            int ko = ks * 8;
            uint32_t a[2][4];
            #pragma unroll
            for (int mf = 0; mf < 2; mf++) {
                int r = wm + mf * 16 + g;
                a[mf][0] = uA[r * 36 + ko + tig];
                a[mf][1] = uA[(r + 8) * 36 + ko + tig];
                a[mf][2] = uA[r * 36 + ko + tig + 4];
                a[mf][3] = uA[(r + 8) * 36 + ko + tig + 4];
            }
            #pragma unroll
            for (int nf = 0; nf < 4; nf++) {
                int cn = wn + nf * 8 + g;
                uint32_t bg0 = uBg[(ko + tig) * 136 + cn];
                uint32_t bg1 = uBg[(ko + tig + 4) * 136 + cn];
                uint32_t bu0 = uBu[(ko + tig) * 136 + cn];
                uint32_t bu1 = uBu[(ko + tig + 4) * 136 + cn];
                mma8(cG[0][nf], a[0], bg0, bg1);
                mma8(cG[1][nf], a[1], bg0, bg1);
                mma8(cU[0][nf], a[0], bu0, bu1);
                mma8(cU[1][nf], a[1], bu0, bu1);
            }
        }

        // store first half; prefetch B second half (k rows 16..31)
        if (more) {
            #pragma unroll
            for (int i = 0; i < 2; i++) {
                cvt_store4r(&nA[arow[i] * 36 + ac4[i] * 4], hA[i]);
                cvt_store4r(&nBg[brow[i] * 136 + bc4[i] * 4], hBg1[i]);
                cvt_store4r(&nBu[brow[i] * 136 + bc4[i] * 4], hBu1[i]);
            }
            #pragma unroll
            for (int i = 0; i < 2; i++) {
                size_t go = (size_t)(k1 + brow[i + 2]) * ldb + n0 + bc4[i + 2] * 4;
                hBg2[i] = *reinterpret_cast<const float4*>(Bg + go);
                hBu2[i] = *reinterpret_cast<const float4*>(Bu + go);
            }
        }

        // compute ks = 2,3
        #pragma unroll
        for (int ks = 2; ks < 4; ks++) {
            int ko = ks * 8;
            uint32_t a[2][4];
            #pragma unroll
            for (int mf = 0; mf < 2; mf++) {
                int r = wm + mf * 16 + g;
                a[mf][0] = uA[r * 36 + ko + tig];
                a[mf][1] = uA[(r + 8) * 36 + ko + tig];
                a[mf][2] = uA[r * 36 + ko + tig + 4];
                a[mf][3] = uA[(r + 8) * 36 + ko + tig + 4];
            }
            #pragma unroll
            for (int nf = 0; nf < 4; nf++) {
                int cn = wn + nf * 8 + g;
                uint32_t bg0 = uBg[(ko + tig) * 136 + cn];
                uint32_t bg1 = uBg[(ko + tig + 4) * 136 + cn];
                uint32_t bu0 = uBu[(ko + tig) * 136 + cn];
                uint32_t bu1 = uBu[(ko + tig + 4) * 136 + cn];
                mma8(cG[0][nf], a[0], bg0, bg1);
                mma8(cG[1][nf], a[1], bg0, bg1);
                mma8(cU[0][nf], a[0], bu0, bu1);
                mma8(cU[1][nf], a[1], bu0, bu1);
            }
        }

        if (more) {
            #pragma unroll
            for (int i = 0; i < 2; i++) {
                cvt_store4r(&nBg[brow[i + 2] * 136 + bc4[i + 2] * 4], hBg2[i]);
                cvt_store4r(&nBu[brow[i + 2] * 136 + bc4[i + 2] * 4], hBu2[i]);
            }
        }
        __syncthreads();
    }

    float* Hbase = expert ? (g_H + (size_t)e * CAP * FDIM) : g_shared_h;
    #pragma unroll
    for (int mf = 0; mf < 2; mf++)
        #pragma unroll
        for (int nf = 0; nf < 4; nf++)
            #pragma unroll
            for (int half = 0; half < 2; half++) {
                int row = wm + mf * 16 + g + half * 8;
                int col = wn + nf * 8 + 2 * tig;
                int m = m0 + row;
                if (m < ne) {
                    float g0 = cG[mf][nf][half * 2],     u0 = cU[mf][nf][half * 2];
                    float g1 = cG[mf][nf][half * 2 + 1], u1 = cU[mf][nf][half * 2 + 1];
                    float2 o;
                    o.x = g0 / (1.f + expf(-g0)) * u0;
                    o.y = g1 / (1.f + expf(-g1)) * u1;
                    *reinterpret_cast<float2*>(Hbase + (size_t)m * FDIM + n0 + col) = o;
                }
            }
}

// ==================== down GEMM (merged shared+experts, atomic add) ====================
// BM=64, BN=128, BK=32, 256 threads, 3 CTAs/SM target. K=768.
// Buffer words: A 2304 + B 4352 = 6656; x2 buffers.
__global__ __launch_bounds__(256, 3)
void down_kernel(const float* __restrict__ WD, const float* __restrict__ WSD,
                 float* __restrict__ out) {
    extern __shared__ float smem[];
    float* bufs = smem;
    int* s_tok = (int*)(smem + 2 * 6656);
    float* s_w = (float*)(s_tok + 64);

    const int tid = threadIdx.x;
    const int z   = blockIdx.z;
    const bool expert = (z < NEXP);
    const int e  = expert ? z : 0;
    const int ne = expert ? min(g_cnt[e], CAP) : T_TOK;
    const int m0 = expert ? blockIdx.y * 64 : (((z - NEXP) * 8 + blockIdx.y) * 64);
    if (m0 >= ne) return;
    const int n0 = blockIdx.x * 128;

    const float* B = expert ? (WD + (size_t)e * FDIM * DDIM) : WSD;
    const float* Abase = expert ? (g_H + (size_t)e * CAP * FDIM) : g_shared_h;

    if (expert) {
        if (tid < 64) {
            int m = m0 + tid;
            s_tok[tid] = (m < ne) ? g_slot_tok[e * CAP + m] : 0;
            s_w[tid]   = (m < ne) ? g_slot_w[e * CAP + m] : 0.f;
        }
        __syncthreads();
    }

    int arow[2], ac4[2], brow[4], bc4[4];
    #pragma unroll
    for (int i = 0; i < 2; i++) {
        int idx = tid + i * 256;
        arow[i] = idx >> 3; ac4[i] = idx & 7;
    }
    #pragma unroll
    for (int i = 0; i < 4; i++) {
        int idx = tid + i * 256;
        brow[i] = idx >> 5; bc4[i] = idx & 31;
    }

    const int lane = tid & 31, warp = tid >> 5;
    const int wm = (warp >> 2) * 32, wn = (warp & 3) * 32;
    const int g = lane >> 2, tig = lane & 3;

    float c[2][4][4] = {};
    float4 hA[2], hB1[2], hB2[2];

    #pragma unroll
    for (int i = 0; i < 2; i++) {
        hA[i]  = *reinterpret_cast<const float4*>(Abase + (size_t)(m0 + arow[i]) * FDIM + ac4[i] * 4);
        hB1[i] = *reinterpret_cast<const float4*>(B + (size_t)brow[i] * DDIM + n0 + bc4[i] * 4);
        hB2[i] = *reinterpret_cast<const float4*>(B + (size_t)brow[i + 2] * DDIM + n0 + bc4[i + 2] * 4);
    }
    {
        float* sA = bufs;
        float* sB = sA + 2304;
        #pragma unroll
        for (int i = 0; i < 2; i++) {
            cvt_store4r(&sA[arow[i] * 36 + ac4[i] * 4], hA[i]);
            cvt_store4r(&sB[brow[i] * 136 + bc4[i] * 4], hB1[i]);
            cvt_store4r(&sB[brow[i + 2] * 136 + bc4[i + 2] * 4], hB2[i]);
        }
    }
    __syncthreads();

    const int NK = FDIM / 32;
    for (int kt = 0; kt < NK; kt++) {
        const bool more = (kt + 1 < NK);
        const int k1 = (kt + 1) * 32;
        const uint32_t* uA = (const uint32_t*)(bufs + (kt & 1) * 6656);
        const uint32_t* uB = uA + 2304;
        float* nA = bufs + ((kt + 1) & 1) * 6656;
        float* nB = nA + 2304;

        if (more) {
            #pragma unroll
            for (int i = 0; i < 2; i++) {
                hA[i]  = *reinterpret_cast<const float4*>(Abase + (size_t)(m0 + arow[i]) * FDIM + k1 + ac4[i] * 4);
                hB1[i] = *reinterpret_cast<const float4*>(B + (size_t)(k1 + brow[i]) * DDIM + n0 + bc4[i] * 4);
            }
        }

        #pragma unroll
        for (int ks = 0; ks < 2; ks++) {
            int ko = ks * 8;
            uint32_t a[2][4];
            #pragma unroll
            for (int mf = 0; mf < 2; mf++) {
                int r = wm + mf * 16 + g;
                a[mf][0] = uA[r * 36 + ko + tig];
                a[mf][1] = uA[(r + 8) * 36 + ko + tig];
                a[mf][2] = uA[r * 36 + ko + tig + 4];
                a[mf][3] = uA[(r + 8) * 36 + ko + tig + 4];
            }
            #pragma unroll
            for (int nf = 0; nf < 4; nf++) {
                int cn = wn + nf * 8 + g;
                uint32_t b0 = uB[(ko + tig) * 136 + cn];
                uint32_t b1 = uB[(ko + tig + 4) * 136 + cn];
                mma8(c[0][nf], a[0], b0, b1);
                mma8(c[1][nf], a[1], b0, b1);
            }
        }

        if (more) {
            #pragma unroll
            for (int i = 0; i < 2; i++) {
                cvt_store4r(&nA[arow[i] * 36 + ac4[i] * 4], hA[i]);
                cvt_store4r(&nB[brow[i] * 136 + bc4[i] * 4], hB1[i]);
            }
            #pragma unroll
            for (int i = 0; i < 2; i++)
                hB2[i] = *reinterpret_cast<const float4*>(B + (size_t)(k1 + brow[i + 2]) * DDIM + n0 + bc4[i + 2] * 4);
        }

        #pragma unroll
        for (int ks = 2; ks < 4; ks++) {
            int ko = ks * 8;
            uint32_t a[2][4];
            #pragma unroll
            for (int mf = 0; mf < 2; mf++) {
                int r = wm + mf * 16 + g;
                a[mf][0] = uA[r * 36 + ko + tig];
                a[mf][1] = uA[(r + 8) * 36 + ko + tig];
                a[mf][2] = uA[r * 36 + ko + tig + 4];
                a[mf][3] = uA[(r + 8) * 36 + ko + tig + 4];
            }
            #pragma unroll
            for (int nf = 0; nf < 4; nf++) {
                int cn = wn + nf * 8 + g;
                uint32_t b0 = uB[(ko + tig) * 136 + cn];
                uint32_t b1 = uB[(ko + tig + 4) * 136 + cn];
                mma8(c[0][nf], a[0], b0, b1);
                mma8(c[1][nf], a[1], b0, b1);
            }
        }

        if (more) {
            #pragma unroll
            for (int i = 0; i < 2; i++)
                cvt_store4r(&nB[brow[i + 2] * 136 + bc4[i + 2] * 4], hB2[i]);
        }
        __syncthreads();
    }

    #pragma unroll
    for (int mf = 0; mf < 2; mf++)
        #pragma unroll
        for (int nf = 0; nf < 4; nf++)
            #pragma unroll
            for (int half = 0; half < 2; half++) {
                int row = wm + mf * 16 + g + half * 8;
                int col = wn + nf * 8 + 2 * tig;
                int m = m0 + row;
                if (m < ne) {
                    float v0 = c[mf][nf][half * 2];
                    float v1 = c[mf][nf][half * 2 + 1];
                    int   tokr = expert ? s_tok[row] : m;
                    float w    = expert ? s_w[row] : 1.f;
                    float* p = out + (size_t)tokr * DDIM + n0 + col;
                    asm volatile("red.global.add.v2.f32 [%0], {%1,%2};"
                                 :: "l"(p), "f"(v0 * w), "f"(v1 * w) : "memory");
                }
            }
}

// -------------------- launch --------------------
extern "C" void kernel_launch(void* const* d_in, const int* in_sizes, int n_in,
                              void* d_out, int out_size) {
    const float* X   = (const float*)d_in[0];   // (B,S,D)
    const float* RW  = (const float*)d_in[1];   // (E,D)
    const float* WG  = (const float*)d_in[2];   // (E,D,F)
    const float* WU  = (const float*)d_in[3];   // (E,D,F)
    const float* WD  = (const float*)d_in[4];   // (E,F,D)
    const float* WSG = (const float*)d_in[5];   // (D, 2*SF)
    const float* WSD = (const float*)d_in[6];   // (SF, D)
    float* out = (float*)d_out;

    const int GUSM = (2 * 11008) * 4 + 64 * 4;   // 88320
    const int DSM  = (2 * 6656) * 4 + 64 * 8;    // 53760

    cudaFuncSetAttribute(gateup_kernel, cudaFuncAttributeMaxDynamicSharedMemorySize, GUSM);
    cudaFuncSetAttribute(down_kernel,   cudaFuncAttributeMaxDynamicSharedMemorySize, DSM);

    zero_cnt_kernel<<<1, 64>>>();
    zero_out_kernel<<<(T_TOK * DDIM / 4) / 256, 256>>>((float4*)out);
    router_kernel<<<T_TOK / 32, 256>>>(X, RW);

    // z in [0,64): experts (8 m-tiles of 64) ; z in [64,68): shared expert (32 m-tiles)
    gateup_kernel<<<dim3(FDIM / 128, 8, NEXP + 4), 256, GUSM>>>(X, WG, WU, WSG);
    down_kernel<<<dim3(DDIM / 128, 8, NEXP + 4), 256, DSM>>>(WD, WSD, out);
}

// round 11
// speedup vs baseline: 1.0318x; 1.0318x over previous
#include <cuda_runtime.h>
#include <cstdint>
#include <math.h>

#define T_TOK 2048
#define DDIM  1024
#define NEXP  64
#define TOPK  8
#define FDIM  768
#define CAP   512

// -------------------- device scratch --------------------
__device__ int   g_cnt[NEXP];
__device__ int   g_slot_tok[NEXP * CAP];
__device__ float g_slot_w[NEXP * CAP];
__device__ float g_H[(size_t)NEXP * CAP * FDIM];        // ~100.7 MB
__device__ float g_shared_h[(size_t)T_TOK * FDIM];      // ~6.3 MB

// -------------------- helpers --------------------
__device__ __forceinline__ uint32_t f2tf32(float x) {
    uint32_t r;
    asm("cvt.rna.tf32.f32 %0, %1;" : "=r"(r) : "f"(x));
    return r;
}

__device__ __forceinline__ void cvt_store4r(float* dst, float4 v) {
    uint4 o;
    o.x = f2tf32(v.x); o.y = f2tf32(v.y); o.z = f2tf32(v.z); o.w = f2tf32(v.w);
    *reinterpret_cast<uint4*>(dst) = o;
}

__device__ __forceinline__ void mma8(float c[4], const uint32_t a[4],
                                     uint32_t b0, uint32_t b1) {
    asm volatile(
        "mma.sync.aligned.m16n8k8.row.col.f32.tf32.tf32.f32 "
        "{%0,%1,%2,%3},{%4,%5,%6,%7},{%8,%9},{%0,%1,%2,%3};\n"
        : "+f"(c[0]), "+f"(c[1]), "+f"(c[2]), "+f"(c[3])
        : "r"(a[0]), "r"(a[1]), "r"(a[2]), "r"(a[3]), "r"(b0), "r"(b1));
}

// -------------------- counters / output reset --------------------
__global__ void zero_cnt_kernel() {
    if (threadIdx.x < NEXP) g_cnt[threadIdx.x] = 0;
}
__global__ void zero_out_kernel(float4* out) {
    out[blockIdx.x * 256 + threadIdx.x] = make_float4(0.f, 0.f, 0.f, 0.f);
}

// -------------------- router --------------------
__global__ __launch_bounds__(256)
void router_kernel(const float* __restrict__ X, const float* __restrict__ RW) {
    __shared__ float xs[32][68];
    __shared__ float rws[64][68];
    __shared__ float probs[32][65];

    const int tid = threadIdx.x;
    const int t0  = blockIdx.x * 32;
    const int t   = tid >> 3;
    const int el  = tid & 7;

    float acc[8] = {0.f,0.f,0.f,0.f,0.f,0.f,0.f,0.f};

    for (int kc = 0; kc < DDIM; kc += 64) {
        #pragma unroll
        for (int i = 0; i < 2; i++) {
            int idx = tid + i * 256;
            int row = idx >> 4, c4 = idx & 15;
            *reinterpret_cast<float4*>(&xs[row][c4 * 4]) =
                *reinterpret_cast<const float4*>(X + (size_t)(t0 + row) * DDIM + kc + c4 * 4);
        }
        #pragma unroll
        for (int i = 0; i < 4; i++) {
            int idx = tid + i * 256;
            int row = idx >> 4, c4 = idx & 15;
            *reinterpret_cast<float4*>(&rws[row][c4 * 4]) =
                *reinterpret_cast<const float4*>(RW + (size_t)row * DDIM + kc + c4 * 4);
        }
        __syncthreads();
        for (int k = 0; k < 64; k++) {
            float xv = xs[t][k];
            #pragma unroll
            for (int j = 0; j < 8; j++) acc[j] += xv * rws[el + 8 * j][k];
        }
        __syncthreads();
    }

    float mx = acc[0];
    #pragma unroll
    for (int j = 1; j < 8; j++) mx = fmaxf(mx, acc[j]);
    #pragma unroll
    for (int m = 1; m < 8; m <<= 1) mx = fmaxf(mx, __shfl_xor_sync(0xffffffffu, mx, m));
    float p[8], s = 0.f;
    #pragma unroll
    for (int j = 0; j < 8; j++) { p[j] = expf(acc[j] - mx); s += p[j]; }
    #pragma unroll
    for (int m = 1; m < 8; m <<= 1) s += __shfl_xor_sync(0xffffffffu, s, m);
    float inv = 1.f / s;
    #pragma unroll
    for (int j = 0; j < 8; j++) probs[t][el + 8 * j] = p[j] * inv;
    __syncthreads();

    if (tid < 32) {
        const int token = t0 + tid;
        float tw[TOPK]; int te[TOPK];
        float psum = 0.f;
        #pragma unroll
        for (int k = 0; k < TOPK; k++) {
            float best = -1.f; int be = 0;
            for (int e2 = 0; e2 < NEXP; e2++) {
                float v = probs[tid][e2];
                if (v > best) { best = v; be = e2; }
            }
            probs[tid][be] = -2.f;
            tw[k] = best; te[k] = be; psum += best;
        }
        float invp = 1.f / psum;
        #pragma unroll
        for (int k = 0; k < TOPK; k++) {
            int pos = atomicAdd(&g_cnt[te[k]], 1);
            if (pos < CAP) {
                g_slot_tok[te[k] * CAP + pos] = token;
                g_slot_w[te[k] * CAP + pos]   = tw[k] * invp;
            }
        }
    }
}

// ==================== fused gate/up GEMM + SiLU (merged shared+experts) ====================
// BM=128, BN=128, BK=32, 512 threads (16 warps 4x4, 32x32 warp tile).
// Pipelined: LDG(kt+1) -> compute(kt) -> STS(kt+1) -> sync. (R8 core)
// Buffer words: A 128*36=4608, Bg 32*136=4352, Bu 4352 => 13312; x2.
__global__ __launch_bounds__(512)
void gateup_kernel(const float* __restrict__ X, const float* __restrict__ WG,
                   const float* __restrict__ WU, const float* __restrict__ WSG) {
    extern __shared__ float smem[];
    float* bufs = smem;
    int* s_tok = (int*)(smem + 2 * 13312);

    const int tid = threadIdx.x;
    const int z   = blockIdx.z;
    const bool expert = (z < NEXP);
    const int e  = expert ? z : 0;
    const int ne = expert ? min(g_cnt[e], CAP) : T_TOK;
    const int m0 = expert ? blockIdx.y * 128 : (((z - NEXP) * 4 + blockIdx.y) * 128);
    if (m0 >= ne) return;
    const int n0 = blockIdx.x * 128;
    const int ldb = expert ? FDIM : 2 * FDIM;

    const float* Bg = expert ? (WG + (size_t)e * DDIM * FDIM) : WSG;
    const float* Bu = expert ? (WU + (size_t)e * DDIM * FDIM) : (WSG + FDIM);

    if (expert) {
        for (int i = tid; i < 128; i += 512) {
            int m = m0 + i;
            s_tok[i] = (m < ne) ? g_slot_tok[e * CAP + m] : 0;
        }
        __syncthreads();
    }

    const float* rp[2];
    int arow[2], ac4[2], brow[2], bc4[2];
    #pragma unroll
    for (int i = 0; i < 2; i++) {
        int idx = tid + i * 512;
        arow[i] = idx >> 3; ac4[i] = idx & 7;
        rp[i] = expert ? (X + (size_t)s_tok[arow[i]] * DDIM)
                       : (X + (size_t)(m0 + arow[i]) * DDIM);
        brow[i] = idx >> 5; bc4[i] = idx & 31;
    }

    const int lane = tid & 31, warp = tid >> 5;
    const int wm = (warp >> 2) * 32, wn = (warp & 3) * 32;
    const int g = lane >> 2, tig = lane & 3;

    float cG[2][4][4] = {};
    float cU[2][4][4] = {};

    float4 hA[2], hBg[2], hBu[2];

    // prologue: load + store tile 0
    #pragma unroll
    for (int i = 0; i < 2; i++)
        hA[i] = *reinterpret_cast<const float4*>(rp[i] + ac4[i] * 4);
    #pragma unroll
    for (int i = 0; i < 2; i++) {
        size_t go = (size_t)brow[i] * ldb + n0 + bc4[i] * 4;
        hBg[i] = *reinterpret_cast<const float4*>(Bg + go);
        hBu[i] = *reinterpret_cast<const float4*>(Bu + go);
    }
    {
        float* sA  = bufs;
        float* sBg = sA + 4608;
        float* sBu = sBg + 4352;
        #pragma unroll
        for (int i = 0; i < 2; i++) {
            cvt_store4r(&sA[arow[i] * 36 + ac4[i] * 4], hA[i]);
            cvt_store4r(&sBg[brow[i] * 136 + bc4[i] * 4], hBg[i]);
            cvt_store4r(&sBu[brow[i] * 136 + bc4[i] * 4], hBu[i]);
        }
    }
    __syncthreads();

    const int NK = DDIM / 32;
    for (int kt = 0; kt < NK; kt++) {
        // issue global loads for tile kt+1 (latency hides under compute)
        if (kt + 1 < NK) {
            const int k1 = (kt + 1) * 32;
            #pragma unroll
            for (int i = 0; i < 2; i++)
                hA[i] = *reinterpret_cast<const float4*>(rp[i] + k1 + ac4[i] * 4);
            #pragma unroll
            for (int i = 0; i < 2; i++) {
                size_t go = (size_t)(k1 + brow[i]) * ldb + n0 + bc4[i] * 4;
                hBg[i] = *reinterpret_cast<const float4*>(Bg + go);
                hBu[i] = *reinterpret_cast<const float4*>(Bu + go);
            }
        }

        // compute tile kt
        {
            const uint32_t* uA  = (const uint32_t*)(bufs + (kt & 1) * 13312);
            const uint32_t* uBg = uA + 4608;
            const uint32_t* uBu = uBg + 4352;
            #pragma unroll
            for (int ks = 0; ks < 4; ks++) {
                int ko = ks * 8;
                uint32_t a[2][4];
                #pragma unroll
                for (int mf = 0; mf < 2; mf++) {
                    int r = wm + mf * 16 + g;
                    a[mf][0] = uA[r * 36 + ko + tig];
                    a[mf][1] = uA[(r + 8) * 36 + ko + tig];
                    a[mf][2] = uA[r * 36 + ko + tig + 4];
                    a[mf][3] = uA[(r + 8) * 36 + ko + tig + 4];
                }
                #pragma unroll
                for (int nf = 0; nf < 4; nf++) {
                    int cn = wn + nf * 8 + g;
                    uint32_t bg0 = uBg[(ko + tig) * 136 + cn];
                    uint32_t bg1 = uBg[(ko + tig + 4) * 136 + cn];
                    uint32_t bu0 = uBu[(ko + tig) * 136 + cn];
                    uint32_t bu1 = uBu[(ko + tig + 4) * 136 + cn];
                    mma8(cG[0][nf], a[0], bg0, bg1);
                    mma8(cG[1][nf], a[1], bg0, bg1);
                    mma8(cU[0][nf], a[0], bu0, bu1);
                    mma8(cU[1][nf], a[1], bu0, bu1);
                }
            }
        }

        // store tile kt+1 into the other buffer
        if (kt + 1 < NK) {
            float* sA  = bufs + ((kt + 1) & 1) * 13312;
            float* sBg = sA + 4608;
            float* sBu = sBg + 4352;
            #pragma unroll
            for (int i = 0; i < 2; i++) {
                cvt_store4r(&sA[arow[i] * 36 + ac4[i] * 4], hA[i]);
                cvt_store4r(&sBg[brow[i] * 136 + bc4[i] * 4], hBg[i]);
                cvt_store4r(&sBu[brow[i] * 136 + bc4[i] * 4], hBu[i]);
            }
        }
        __syncthreads();
    }

    float* Hbase = expert ? (g_H + (size_t)e * CAP * FDIM) : g_shared_h;
    #pragma unroll
    for (int mf = 0; mf < 2; mf++)
        #pragma unroll
        for (int nf = 0; nf < 4; nf++)
            #pragma unroll
            for (int half = 0; half < 2; half++) {
                int row = wm + mf * 16 + g + half * 8;
                int col = wn + nf * 8 + 2 * tig;
                int m = m0 + row;
                if (m < ne) {
                    float g0 = cG[mf][nf][half * 2],     u0 = cU[mf][nf][half * 2];
                    float g1 = cG[mf][nf][half * 2 + 1], u1 = cU[mf][nf][half * 2 + 1];
                    float2 o;
                    o.x = g0 / (1.f + expf(-g0)) * u0;
                    o.y = g1 / (1.f + expf(-g1)) * u1;
                    *reinterpret_cast<float2*>(Hbase + (size_t)m * FDIM + n0 + col) = o;
                }
            }
}

// ==================== down GEMM (merged shared+experts, atomic add) ====================
// K = FDIM = 768. Buffer words: A 4608 + B 4352 = 8960; x2. (R8 core)
__global__ __launch_bounds__(512)
void down_kernel(const float* __restrict__ WD, const float* __restrict__ WSD,
                 float* __restrict__ out) {
    extern __shared__ float smem[];
    float* bufs = smem;
    int* s_tok = (int*)(smem + 2 * 8960);
    float* s_w = (float*)(s_tok + 128);

    const int tid = threadIdx.x;
    const int z   = blockIdx.z;
    const bool expert = (z < NEXP);
    const int e  = expert ? z : 0;
    const int ne = expert ? min(g_cnt[e], CAP) : T_TOK;
    const int m0 = expert ? blockIdx.y * 128 : (((z - NEXP) * 4 + blockIdx.y) * 128);
    if (m0 >= ne) return;
    const int n0 = blockIdx.x * 128;

    const float* B = expert ? (WD + (size_t)e * FDIM * DDIM) : WSD;
    const float* Abase = expert ? (g_H + (size_t)e * CAP * FDIM) : g_shared_h;

    if (expert) {
        for (int i = tid; i < 128; i += 512) {
            int m = m0 + i;
            s_tok[i] = (m < ne) ? g_slot_tok[e * CAP + m] : 0;
            s_w[i]   = (m < ne) ? g_slot_w[e * CAP + m] : 0.f;
        }
        __syncthreads();
    }

    int arow[2], ac4[2], brow[2], bc4[2];
    #pragma unroll
    for (int i = 0; i < 2; i++) {
        int idx = tid + i * 512;
        arow[i] = idx >> 3; ac4[i] = idx & 7;
        brow[i] = idx >> 5; bc4[i] = idx & 31;
    }

    const int lane = tid & 31, warp = tid >> 5;
    const int wm = (warp >> 2) * 32, wn = (warp & 3) * 32;
    const int g = lane >> 2, tig = lane & 3;

    float c[2][4][4] = {};
    float4 hA[2], hB[2];

    // prologue: tile 0
    #pragma unroll
    for (int i = 0; i < 2; i++) {
        hA[i] = *reinterpret_cast<const float4*>(Abase + (size_t)(m0 + arow[i]) * FDIM + ac4[i] * 4);
        hB[i] = *reinterpret_cast<const float4*>(B + (size_t)brow[i] * DDIM + n0 + bc4[i] * 4);
    }
    {
        float* sA = bufs;
        float* sB = sA + 4608;
        #pragma unroll
        for (int i = 0; i < 2; i++) {
            cvt_store4r(&sA[arow[i] * 36 + ac4[i] * 4], hA[i]);
            cvt_store4r(&sB[brow[i] * 136 + bc4[i] * 4], hB[i]);
        }
    }
    __syncthreads();

    const int NK = FDIM / 32;
    for (int kt = 0; kt < NK; kt++) {
        if (kt + 1 < NK) {
            const int k1 = (kt + 1) * 32;
            #pragma unroll
            for (int i = 0; i < 2; i++) {
                hA[i] = *reinterpret_cast<const float4*>(Abase + (size_t)(m0 + arow[i]) * FDIM + k1 + ac4[i] * 4);
                hB[i] = *reinterpret_cast<const float4*>(B + (size_t)(k1 + brow[i]) * DDIM + n0 + bc4[i] * 4);
            }
        }

        {
            const uint32_t* uA = (const uint32_t*)(bufs + (kt & 1) * 8960);
            const uint32_t* uB = uA + 4608;
            #pragma unroll
            for (int ks = 0; ks < 4; ks++) {
                int ko = ks * 8;
                uint32_t a[2][4];
                #pragma unroll
                for (int mf = 0; mf < 2; mf++) {
                    int r = wm + mf * 16 + g;
                    a[mf][0] = uA[r * 36 + ko + tig];
                    a[mf][1] = uA[(r + 8) * 36 + ko + tig];
                    a[mf][2] = uA[r * 36 + ko + tig + 4];
                    a[mf][3] = uA[(r + 8) * 36 + ko + tig + 4];
                }
                #pragma unroll
                for (int nf = 0; nf < 4; nf++) {
                    int cn = wn + nf * 8 + g;
                    uint32_t b0 = uB[(ko + tig) * 136 + cn];
                    uint32_t b1 = uB[(ko + tig + 4) * 136 + cn];
                    mma8(c[0][nf], a[0], b0, b1);
                    mma8(c[1][nf], a[1], b0, b1);
                }
            }
        }

        if (kt + 1 < NK) {
            float* sA = bufs + ((kt + 1) & 1) * 8960;
            float* sB = sA + 4608;
            #pragma unroll
            for (int i = 0; i < 2; i++) {
                cvt_store4r(&sA[arow[i] * 36 + ac4[i] * 4], hA[i]);
                cvt_store4r(&sB[brow[i] * 136 + bc4[i] * 4], hB[i]);
            }
        }
        __syncthreads();
    }

    #pragma unroll
    for (int mf = 0; mf < 2; mf++)
        #pragma unroll
        for (int nf = 0; nf < 4; nf++)
            #pragma unroll
            for (int half = 0; half < 2; half++) {
                int row = wm + mf * 16 + g + half * 8;
                int col = wn + nf * 8 + 2 * tig;
                int m = m0 + row;
                if (m < ne) {
                    float v0 = c[mf][nf][half * 2];
                    float v1 = c[mf][nf][half * 2 + 1];
                    int   tokr = expert ? s_tok[row] : m;
                    float w    = expert ? s_w[row] : 1.f;
                    float* p = out + (size_t)tokr * DDIM + n0 + col;
                    asm volatile("red.global.add.v2.f32 [%0], {%1,%2};"
                                 :: "l"(p), "f"(v0 * w), "f"(v1 * w) : "memory");
                }
            }
}

// -------------------- launch --------------------
extern "C" void kernel_launch(void* const* d_in, const int* in_sizes, int n_in,
                              void* d_out, int out_size) {
    const float* X   = (const float*)d_in[0];   // (B,S,D)
    const float* RW  = (const float*)d_in[1];   // (E,D)
    const float* WG  = (const float*)d_in[2];   // (E,D,F)
    const float* WU  = (const float*)d_in[3];   // (E,D,F)
    const float* WD  = (const float*)d_in[4];   // (E,F,D)
    const float* WSG = (const float*)d_in[5];   // (D, 2*SF)
    const float* WSD = (const float*)d_in[6];   // (SF, D)
    float* out = (float*)d_out;

    const int GUSM = (2 * 13312) * 4 + 128 * 4;        // 107008
    const int DSM  = (2 * 8960) * 4 + 128 * 8;         // 72704

    cudaFuncSetAttribute(gateup_kernel, cudaFuncAttributeMaxDynamicSharedMemorySize, GUSM);
    cudaFuncSetAttribute(down_kernel,   cudaFuncAttributeMaxDynamicSharedMemorySize, DSM);

    zero_cnt_kernel<<<1, 64>>>();
    zero_out_kernel<<<(T_TOK * DDIM / 4) / 256, 256>>>((float4*)out);
    router_kernel<<<T_TOK / 32, 256>>>(X, RW);

    // z in [0,64): experts (4 m-tiles of 128) ; z in [64,68): shared expert (16 m-tiles)
    gateup_kernel<<<dim3(FDIM / 128, 4, NEXP + 4), 512, GUSM>>>(X, WG, WU, WSG);
    down_kernel<<<dim3(DDIM / 128, 4, NEXP + 4), 512, DSM>>>(WD, WSD, out);
}

// round 12
// speedup vs baseline: 1.0472x; 1.0149x over previous
#include <cuda_runtime.h>
#include <cstdint>
#include <math.h>

#define T_TOK 2048
#define DDIM  1024
#define NEXP  64
#define TOPK  8
#define FDIM  768
#define CAP   512

// -------------------- device scratch --------------------
__device__ int   g_cnt[NEXP];
__device__ int   g_slot_tok[NEXP * CAP];
__device__ float g_slot_w[NEXP * CAP];
__device__ float g_H[(size_t)NEXP * CAP * FDIM];        // ~100.7 MB
__device__ float g_shared_h[(size_t)T_TOK * FDIM];      // ~6.3 MB

// -------------------- helpers --------------------
__device__ __forceinline__ uint32_t f2tf32(float x) {
    uint32_t r;
    asm("cvt.rna.tf32.f32 %0, %1;" : "=r"(r) : "f"(x));
    return r;
}

__device__ __forceinline__ void cvt_store4r(float* dst, float4 v) {
    uint4 o;
    o.x = f2tf32(v.x); o.y = f2tf32(v.y); o.z = f2tf32(v.z); o.w = f2tf32(v.w);
    *reinterpret_cast<uint4*>(dst) = o;
}

__device__ __forceinline__ void mma8(float c[4], const uint32_t a[4],
                                     uint32_t b0, uint32_t b1) {
    asm volatile(
        "mma.sync.aligned.m16n8k8.row.col.f32.tf32.tf32.f32 "
        "{%0,%1,%2,%3},{%4,%5,%6,%7},{%8,%9},{%0,%1,%2,%3};\n"
        : "+f"(c[0]), "+f"(c[1]), "+f"(c[2]), "+f"(c[3])
        : "r"(a[0]), "r"(a[1]), "r"(a[2]), "r"(a[3]), "r"(b0), "r"(b1));
}

// -------------------- counters reset --------------------
__global__ void zero_cnt_kernel() {
    if (threadIdx.x < NEXP) g_cnt[threadIdx.x] = 0;
}

// -------------------- router --------------------
__global__ __launch_bounds__(256)
void router_kernel(const float* __restrict__ X, const float* __restrict__ RW) {
    __shared__ float xs[32][68];
    __shared__ float rws[64][68];
    __shared__ float probs[32][65];

    const int tid = threadIdx.x;
    const int t0  = blockIdx.x * 32;
    const int t   = tid >> 3;
    const int el  = tid & 7;

    float acc[8] = {0.f,0.f,0.f,0.f,0.f,0.f,0.f,0.f};

    for (int kc = 0; kc < DDIM; kc += 64) {
        #pragma unroll
        for (int i = 0; i < 2; i++) {
            int idx = tid + i * 256;
            int row = idx >> 4, c4 = idx & 15;
            *reinterpret_cast<float4*>(&xs[row][c4 * 4]) =
                *reinterpret_cast<const float4*>(X + (size_t)(t0 + row) * DDIM + kc + c4 * 4);
        }
        #pragma unroll
        for (int i = 0; i < 4; i++) {
            int idx = tid + i * 256;
            int row = idx >> 4, c4 = idx & 15;
            *reinterpret_cast<float4*>(&rws[row][c4 * 4]) =
                *reinterpret_cast<const float4*>(RW + (size_t)row * DDIM + kc + c4 * 4);
        }
        __syncthreads();
        for (int k = 0; k < 64; k++) {
            float xv = xs[t][k];
            #pragma unroll
            for (int j = 0; j < 8; j++) acc[j] += xv * rws[el + 8 * j][k];
        }
        __syncthreads();
    }

    float mx = acc[0];
    #pragma unroll
    for (int j = 1; j < 8; j++) mx = fmaxf(mx, acc[j]);
    #pragma unroll
    for (int m = 1; m < 8; m <<= 1) mx = fmaxf(mx, __shfl_xor_sync(0xffffffffu, mx, m));
    float p[8], s = 0.f;
    #pragma unroll
    for (int j = 0; j < 8; j++) { p[j] = expf(acc[j] - mx); s += p[j]; }
    #pragma unroll
    for (int m = 1; m < 8; m <<= 1) s += __shfl_xor_sync(0xffffffffu, s, m);
    float inv = 1.f / s;
    #pragma unroll
    for (int j = 0; j < 8; j++) probs[t][el + 8 * j] = p[j] * inv;
    __syncthreads();

    if (tid < 32) {
        const int token = t0 + tid;
        float tw[TOPK]; int te[TOPK];
        float psum = 0.f;
        #pragma unroll
        for (int k = 0; k < TOPK; k++) {
            float best = -1.f; int be = 0;
            for (int e2 = 0; e2 < NEXP; e2++) {
                float v = probs[tid][e2];
                if (v > best) { best = v; be = e2; }
            }
            probs[tid][be] = -2.f;
            tw[k] = best; te[k] = be; psum += best;
        }
        float invp = 1.f / psum;
        #pragma unroll
        for (int k = 0; k < TOPK; k++) {
            int pos = atomicAdd(&g_cnt[te[k]], 1);
            if (pos < CAP) {
                g_slot_tok[te[k] * CAP + pos] = token;
                g_slot_w[te[k] * CAP + pos]   = tw[k] * invp;
            }
        }
    }
}

// ==================== fused gate/up GEMM + SiLU ====================
// BM=128, BN=128, BK=64, 512 threads (16 warps 4x4, 32x32 warp tile).
// Pipelined with split prefetch:
//   LDG(A,Bhalf1 of kt+1) -> ks0..3(kt) -> STS(A,Bh1) + LDG(Bhalf2) -> ks4..7(kt) -> STS(Bh2) -> sync
// Buffer words: A 128*68=8704, Bg 64*136=8704, Bu 8704 => 26112; x2 buffers = 204 KB.
template<bool EXPERT>
__global__ __launch_bounds__(512)
void gateup_kernel(const float* __restrict__ X, const float* __restrict__ WG,
                   const float* __restrict__ WU, int ldb) {
    extern __shared__ float smem[];
    float* bufs = smem;
    int* s_tok = (int*)(smem + 2 * 26112);

    const int tid = threadIdx.x;
    const int e  = EXPERT ? blockIdx.z : 0;
    const int ne = EXPERT ? min(g_cnt[e], CAP) : T_TOK;
    const int m0 = blockIdx.y * 128;
    if (m0 >= ne) return;
    const int n0 = blockIdx.x * 128;

    const float* Bg = EXPERT ? (WG + (size_t)e * DDIM * FDIM) : WG;
    const float* Bu = EXPERT ? (WU + (size_t)e * DDIM * FDIM) : WU;

    if (EXPERT) {
        for (int i = tid; i < 128; i += 512) {
            int m = m0 + i;
            s_tok[i] = (m < ne) ? g_slot_tok[e * CAP + m] : 0;
        }
        __syncthreads();
    }

    // A producer: 4 float4/thread. idx = tid+i*512 -> row = idx>>4 (0..127), q = idx&15
    const float* rpA[4];
    int arow[4], aq[4];
    #pragma unroll
    for (int i = 0; i < 4; i++) {
        int idx = tid + i * 512;
        arow[i] = idx >> 4; aq[i] = idx & 15;
        rpA[i] = EXPERT ? (X + (size_t)s_tok[arow[i]] * DDIM)
                        : (X + (size_t)(m0 + arow[i]) * DDIM);
    }
    // B producer: 4 float4/thread/matrix. idx = tid+i*512 -> row = idx>>5 (0..63), c4 = idx&31
    int brow[4], bc4[4];
    #pragma unroll
    for (int i = 0; i < 4; i++) {
        int idx = tid + i * 512;
        brow[i] = idx >> 5; bc4[i] = idx & 31;
    }

    const int lane = tid & 31, warp = tid >> 5;
    const int wm = (warp >> 2) * 32, wn = (warp & 3) * 32;
    const int g = lane >> 2, tig = lane & 3;

    float cG[2][4][4] = {};
    float cU[2][4][4] = {};

    float4 hA[4], hBg[2], hBu[2];

    // ---- prologue: full tile 0 ----
    {
        float* sA  = bufs;
        float* sBg = sA + 8704;
        float* sBu = sBg + 8704;
        #pragma unroll
        for (int i = 0; i < 4; i++)
            hA[i] = *reinterpret_cast<const float4*>(rpA[i] + aq[i] * 4);
        #pragma unroll
        for (int i = 0; i < 4; i++)
            cvt_store4r(&sA[arow[i] * 68 + aq[i] * 4], hA[i]);
        #pragma unroll
        for (int h = 0; h < 2; h++) {
            #pragma unroll
            for (int i = 0; i < 2; i++) {
                int j = h * 2 + i;
                size_t go = (size_t)brow[j] * ldb + n0 + bc4[j] * 4;
                hBg[i] = *reinterpret_cast<const float4*>(Bg + go);
                hBu[i] = *reinterpret_cast<const float4*>(Bu + go);
            }
            #pragma unroll
            for (int i = 0; i < 2; i++) {
                int j = h * 2 + i;
                cvt_store4r(&sBg[brow[j] * 136 + bc4[j] * 4], hBg[i]);
                cvt_store4r(&sBu[brow[j] * 136 + bc4[j] * 4], hBu[i]);
            }
        }
    }
    __syncthreads();

    const int NK = DDIM / 64;
    for (int kt = 0; kt < NK; kt++) {
        const bool more = (kt + 1 < NK);
        const int k1 = (kt + 1) * 64;
        const uint32_t* uA  = (const uint32_t*)(bufs + (kt & 1) * 26112);
        const uint32_t* uBg = uA + 8704;
        const uint32_t* uBu = uBg + 8704;
        float* nA  = bufs + ((kt + 1) & 1) * 26112;
        float* nBg = nA + 8704;
        float* nBu = nBg + 8704;

        // prefetch A (all) + B first half (k rows 0..31) of next tile
        if (more) {
            #pragma unroll
            for (int i = 0; i < 4; i++)
                hA[i] = *reinterpret_cast<const float4*>(rpA[i] + k1 + aq[i] * 4);
            #pragma unroll
            for (int i = 0; i < 2; i++) {
                size_t go = (size_t)(k1 + brow[i]) * ldb + n0 + bc4[i] * 4;
                hBg[i] = *reinterpret_cast<const float4*>(Bg + go);
                hBu[i] = *reinterpret_cast<const float4*>(Bu + go);
            }
        }

        // compute ks = 0..3 (k 0..31 of this tile)
        #pragma unroll
        for (int ks = 0; ks < 4; ks++) {
            int ko = ks * 8;
            uint32_t a[2][4];
            #pragma unroll
            for (int mf = 0; mf < 2; mf++) {
                int r = wm + mf * 16 + g;
                a[mf][0] = uA[r * 68 + ko + tig];
                a[mf][1] = uA[(r + 8) * 68 + ko + tig];
                a[mf][2] = uA[r * 68 + ko + tig + 4];
                a[mf][3] = uA[(r + 8) * 68 + ko + tig + 4];
            }
            #pragma unroll
            for (int nf = 0; nf < 4; nf++) {
                int cn = wn + nf * 8 + g;
                uint32_t bg0 = uBg[(ko + tig) * 136 + cn];
                uint32_t bg1 = uBg[(ko + tig + 4) * 136 + cn];
                uint32_t bu0 = uBu[(ko + tig) * 136 + cn];
                uint32_t bu1 = uBu[(ko + tig + 4) * 136 + cn];
                mma8(cG[0][nf], a[0], bg0, bg1);
                mma8(cG[1][nf], a[1], bg0, bg1);
                mma8(cU[0][nf], a[0], bu0, bu1);
                mma8(cU[1][nf], a[1], bu0, bu1);
            }
        }

        // store A + B first half; prefetch B second half (k rows 32..63)
        if (more) {
            #pragma unroll
            for (int i = 0; i < 4; i++)
                cvt_store4r(&nA[arow[i] * 68 + aq[i] * 4], hA[i]);
            #pragma unroll
            for (int i = 0; i < 2; i++) {
                cvt_store4r(&nBg[brow[i] * 136 + bc4[i] * 4], hBg[i]);
                cvt_store4r(&nBu[brow[i] * 136 + bc4[i] * 4], hBu[i]);
            }
            #pragma unroll
            for (int i = 0; i < 2; i++) {
                int j = i + 2;
                size_t go = (size_t)(k1 + brow[j]) * ldb + n0 + bc4[j] * 4;
                hBg[i] = *reinterpret_cast<const float4*>(Bg + go);
                hBu[i] = *reinterpret_cast<const float4*>(Bu + go);
            }
        }

        // compute ks = 4..7 (k 32..63 of this tile)
        #pragma unroll
        for (int ks = 4; ks < 8; ks++) {
            int ko = ks * 8;
            uint32_t a[2][4];
            #pragma unroll
            for (int mf = 0; mf < 2; mf++) {
                int r = wm + mf * 16 + g;
                a[mf][0] = uA[r * 68 + ko + tig];
                a[mf][1] = uA[(r + 8) * 68 + ko + tig];
                a[mf][2] = uA[r * 68 + ko + tig + 4];
                a[mf][3] = uA[(r + 8) * 68 + ko + tig + 4];
            }
            #pragma unroll
            for (int nf = 0; nf < 4; nf++) {
                int cn = wn + nf * 8 + g;
                uint32_t bg0 = uBg[(ko + tig) * 136 + cn];
                uint32_t bg1 = uBg[(ko + tig + 4) * 136 + cn];
                uint32_t bu0 = uBu[(ko + tig) * 136 + cn];
                uint32_t bu1 = uBu[(ko + tig + 4) * 136 + cn];
                mma8(cG[0][nf], a[0], bg0, bg1);
                mma8(cG[1][nf], a[1], bg0, bg1);
                mma8(cU[0][nf], a[0], bu0, bu1);
                mma8(cU[1][nf], a[1], bu0, bu1);
            }
        }

        // store B second half
        if (more) {
            #pragma unroll
            for (int i = 0; i < 2; i++) {
                int j = i + 2;
                cvt_store4r(&nBg[brow[j] * 136 + bc4[j] * 4], hBg[i]);
                cvt_store4r(&nBu[brow[j] * 136 + bc4[j] * 4], hBu[i]);
            }
        }
        __syncthreads();
    }

    float* Hbase = EXPERT ? (g_H + (size_t)e * CAP * FDIM) : g_shared_h;
    #pragma unroll
    for (int mf = 0; mf < 2; mf++)
        #pragma unroll
        for (int nf = 0; nf < 4; nf++)
            #pragma unroll
            for (int half = 0; half < 2; half++) {
                int row = wm + mf * 16 + g + half * 8;
                int col = wn + nf * 8 + 2 * tig;
                int m = m0 + row;
                if (m < ne) {
                    float g0 = cG[mf][nf][half * 2],     u0 = cU[mf][nf][half * 2];
                    float g1 = cG[mf][nf][half * 2 + 1], u1 = cU[mf][nf][half * 2 + 1];
                    float2 o;
                    o.x = g0 / (1.f + expf(-g0)) * u0;
                    o.y = g1 / (1.f + expf(-g1)) * u1;
                    *reinterpret_cast<float2*>(Hbase + (size_t)m * FDIM + n0 + col) = o;
                }
            }
}

// ==================== down GEMM ====================
// BM=128, BN=128, BK=64, 512 threads. K = 768 -> 12 k-tiles.
// Buffer words: A 128*68=8704 + B 64*136=8704 = 17408; x2 = 137 KB.
template<bool EXPERT>
__global__ __launch_bounds__(512)
void down_kernel(const float* __restrict__ WD, float* __restrict__ out) {
    extern __shared__ float smem[];
    float* bufs = smem;
    int* s_tok = (int*)(smem + 2 * 17408);
    float* s_w = (float*)(s_tok + 128);

    const int tid = threadIdx.x;
    const int e  = EXPERT ? blockIdx.z : 0;
    const int ne = EXPERT ? min(g_cnt[e], CAP) : T_TOK;
    const int m0 = blockIdx.y * 128;
    if (m0 >= ne) return;
    const int n0 = blockIdx.x * 128;

    const float* B = EXPERT ? (WD + (size_t)e * FDIM * DDIM) : WD;
    const float* Abase = EXPERT ? (g_H + (size_t)e * CAP * FDIM) : g_shared_h;

    if (EXPERT) {
        for (int i = tid; i < 128; i += 512) {
            int m = m0 + i;
            s_tok[i] = (m < ne) ? g_slot_tok[e * CAP + m] : 0;
            s_w[i]   = (m < ne) ? g_slot_w[e * CAP + m] : 0.f;
        }
        __syncthreads();
    }

    int arow[4], aq[4], brow[4], bc4[4];
    #pragma unroll
    for (int i = 0; i < 4; i++) {
        int idx = tid + i * 512;
        arow[i] = idx >> 4; aq[i] = idx & 15;
        brow[i] = idx >> 5; bc4[i] = idx & 31;
    }

    const int lane = tid & 31, warp = tid >> 5;
    const int wm = (warp >> 2) * 32, wn = (warp & 3) * 32;
    const int g = lane >> 2, tig = lane & 3;

    float c[2][4][4] = {};
    float4 hA[4], hB[2];

    // ---- prologue: full tile 0 ----
    {
        float* sA = bufs;
        float* sB = sA + 8704;
        #pragma unroll
        for (int i = 0; i < 4; i++)
            hA[i] = *reinterpret_cast<const float4*>(Abase + (size_t)(m0 + arow[i]) * FDIM + aq[i] * 4);
        #pragma unroll
        for (int i = 0; i < 4; i++)
            cvt_store4r(&sA[arow[i] * 68 + aq[i] * 4], hA[i]);
        #pragma unroll
        for (int h = 0; h < 2; h++) {
            #pragma unroll
            for (int i = 0; i < 2; i++) {
                int j = h * 2 + i;
                hB[i] = *reinterpret_cast<const float4*>(B + (size_t)brow[j] * DDIM + n0 + bc4[j] * 4);
            }
            #pragma unroll
            for (int i = 0; i < 2; i++) {
                int j = h * 2 + i;
                cvt_store4r(&sB[brow[j] * 136 + bc4[j] * 4], hB[i]);
            }
        }
    }
    __syncthreads();

    const int NK = FDIM / 64;
    for (int kt = 0; kt < NK; kt++) {
        const bool more = (kt + 1 < NK);
        const int k1 = (kt + 1) * 64;
        const uint32_t* uA = (const uint32_t*)(bufs + (kt & 1) * 17408);
        const uint32_t* uB = uA + 8704;
        float* nA = bufs + ((kt + 1) & 1) * 17408;
        float* nB = nA + 8704;

        if (more) {
            #pragma unroll
            for (int i = 0; i < 4; i++)
                hA[i] = *reinterpret_cast<const float4*>(Abase + (size_t)(m0 + arow[i]) * FDIM + k1 + aq[i] * 4);
            #pragma unroll
            for (int i = 0; i < 2; i++)
                hB[i] = *reinterpret_cast<const float4*>(B + (size_t)(k1 + brow[i]) * DDIM + n0 + bc4[i] * 4);
        }

        #pragma unroll
        for (int ks = 0; ks < 4; ks++) {
            int ko = ks * 8;
            uint32_t a[2][4];
            #pragma unroll
            for (int mf = 0; mf < 2; mf++) {
                int r = wm + mf * 16 + g;
                a[mf][0] = uA[r * 68 + ko + tig];
                a[mf][1] = uA[(r + 8) * 68 + ko + tig];
                a[mf][2] = uA[r * 68 + ko + tig + 4];
                a[mf][3] = uA[(r + 8) * 68 + ko + tig + 4];
            }
            #pragma unroll
            for (int nf = 0; nf < 4; nf++) {
                int cn = wn + nf * 8 + g;
                uint32_t b0 = uB[(ko + tig) * 136 + cn];
                uint32_t b1 = uB[(ko + tig + 4) * 136 + cn];
                mma8(c[0][nf], a[0], b0, b1);
                mma8(c[1][nf], a[1], b0, b1);
            }
        }

        if (more) {
            #pragma unroll
            for (int i = 0; i < 4; i++)
                cvt_store4r(&nA[arow[i] * 68 + aq[i] * 4], hA[i]);
            #pragma unroll
            for (int i = 0; i < 2; i++)
                cvt_store4r(&nB[brow[i] * 136 + bc4[i] * 4], hB[i]);
            #pragma unroll
            for (int i = 0; i < 2; i++) {
                int j = i + 2;
                hB[i] = *reinterpret_cast<const float4*>(B + (size_t)(k1 + brow[j]) * DDIM + n0 + bc4[j] * 4);
            }
        }

        #pragma unroll
        for (int ks = 4; ks < 8; ks++) {
            int ko = ks * 8;
            uint32_t a[2][4];
            #pragma unroll
            for (int mf = 0; mf < 2; mf++) {
                int r = wm + mf * 16 + g;
                a[mf][0] = uA[r * 68 + ko + tig];
                a[mf][1] = uA[(r + 8) * 68 + ko + tig];
                a[mf][2] = uA[r * 68 + ko + tig + 4];
                a[mf][3] = uA[(r + 8) * 68 + ko + tig + 4];
            }
            #pragma unroll
            for (int nf = 0; nf < 4; nf++) {
                int cn = wn + nf * 8 + g;
                uint32_t b0 = uB[(ko + tig) * 136 + cn];
                uint32_t b1 = uB[(ko + tig + 4) * 136 + cn];
                mma8(c[0][nf], a[0], b0, b1);
                mma8(c[1][nf], a[1], b0, b1);
            }
        }

        if (more) {
            #pragma unroll
            for (int i = 0; i < 2; i++) {
                int j = i + 2;
                cvt_store4r(&nB[brow[j] * 136 + bc4[j] * 4], hB[i]);
            }
        }
        __syncthreads();
    }

    #pragma unroll
    for (int mf = 0; mf < 2; mf++)
        #pragma unroll
        for (int nf = 0; nf < 4; nf++)
            #pragma unroll
            for (int half = 0; half < 2; half++) {
                int row = wm + mf * 16 + g + half * 8;
                int col = wn + nf * 8 + 2 * tig;
                int m = m0 + row;
                if (m < ne) {
                    float v0 = c[mf][nf][half * 2];
                    float v1 = c[mf][nf][half * 2 + 1];
                    if (EXPERT) {
                        float w = s_w[row];
                        float* p = out + (size_t)s_tok[row] * DDIM + n0 + col;
                        asm volatile("red.global.add.v2.f32 [%0], {%1,%2};"
                                     :: "l"(p), "f"(v0 * w), "f"(v1 * w) : "memory");
                    } else {
                        float2* p = (float2*)(out + (size_t)m * DDIM + n0 + col);
                        *p = make_float2(v0, v1);
                    }
                }
            }
}

// -------------------- launch --------------------
extern "C" void kernel_launch(void* const* d_in, const int* in_sizes, int n_in,
                              void* d_out, int out_size) {
    const float* X   = (const float*)d_in[0];   // (B,S,D)
    const float* RW  = (const float*)d_in[1];   // (E,D)
    const float* WG  = (const float*)d_in[2];   // (E,D,F)
    const float* WU  = (const float*)d_in[3];   // (E,D,F)
    const float* WD  = (const float*)d_in[4];   // (E,F,D)
    const float* WSG = (const float*)d_in[5];   // (D, 2*SF)
    const float* WSD = (const float*)d_in[6];   // (SF, D)
    float* out = (float*)d_out;

    const int GUSM = (2 * 26112) * 4 + 128 * 4;   // 209408
    const int DSM  = (2 * 17408) * 4 + 128 * 8;   // 140288

    cudaFuncSetAttribute(gateup_kernel<false>, cudaFuncAttributeMaxDynamicSharedMemorySize, GUSM);
    cudaFuncSetAttribute(gateup_kernel<true>,  cudaFuncAttributeMaxDynamicSharedMemorySize, GUSM);
    cudaFuncSetAttribute(down_kernel<false>,   cudaFuncAttributeMaxDynamicSharedMemorySize, DSM);
    cudaFuncSetAttribute(down_kernel<true>,    cudaFuncAttributeMaxDynamicSharedMemorySize, DSM);

    zero_cnt_kernel<<<1, 64>>>();
    router_kernel<<<T_TOK / 32, 256>>>(X, RW);

    // shared expert gate/up: gate cols [0,768), up cols [768,1536)
    gateup_kernel<false><<<dim3(FDIM / 128, T_TOK / 128, 1), 512, GUSM>>>(X, WSG, WSG + FDIM, 2 * FDIM);
    // routed experts gate/up
    gateup_kernel<true><<<dim3(FDIM / 128, CAP / 128, NEXP), 512, GUSM>>>(X, WG, WU, FDIM);

    // shared expert down (initializes every element of out)
    down_kernel<false><<<dim3(DDIM / 128, T_TOK / 128, 1), 512, DSM>>>(WSD, out);
    // routed experts down (weighted atomic scatter)
    down_kernel<true><<<dim3(DDIM / 128, CAP / 128, NEXP), 512, DSM>>>(WD, out);
}

// round 13
// speedup vs baseline: 1.6409x; 1.5669x over previous
#include <cuda_runtime.h>
#include <cuda_fp16.h>
#include <cstdint>
#include <math.h>

#define T_TOK 2048
#define DDIM  1024
#define NEXP  64
#define TOPK  8
#define FDIM  768
#define CAP   512

// -------------------- device scratch --------------------
__device__ int    g_cnt[NEXP];
__device__ int    g_slot_tok[NEXP * CAP];
__device__ float  g_slot_w[NEXP * CAP];
__device__ __half g_H[(size_t)NEXP * CAP * FDIM];        // ~50 MB
__device__ __half g_shared_h[(size_t)T_TOK * FDIM];      // ~3 MB

// -------------------- helpers --------------------
__device__ __forceinline__ uint32_t pack_h2(float a, float b) {
    __half2 h = __floats2half2_rn(a, b);
    return *reinterpret_cast<uint32_t*>(&h);
}

// fp16 mma: D(f32) = A(f16) * B(f16) + C(f32), m16n8k16
__device__ __forceinline__ void mma16(float c[4], const uint32_t a[4],
                                      uint32_t b0, uint32_t b1) {
    asm volatile(
        "mma.sync.aligned.m16n8k16.row.col.f32.f16.f16.f32 "
        "{%0,%1,%2,%3},{%4,%5,%6,%7},{%8,%9},{%0,%1,%2,%3};\n"
        : "+f"(c[0]), "+f"(c[1]), "+f"(c[2]), "+f"(c[3])
        : "r"(a[0]), "r"(a[1]), "r"(a[2]), "r"(a[3]), "r"(b0), "r"(b1));
}

// -------------------- counters reset --------------------
__global__ void zero_cnt_kernel() {
    if (threadIdx.x < NEXP) g_cnt[threadIdx.x] = 0;
}

// -------------------- router --------------------
__global__ __launch_bounds__(256)
void router_kernel(const float* __restrict__ X, const float* __restrict__ RW) {
    __shared__ float xs[32][68];
    __shared__ float rws[64][68];
    __shared__ float probs[32][65];

    const int tid = threadIdx.x;
    const int t0  = blockIdx.x * 32;
    const int t   = tid >> 3;
    const int el  = tid & 7;

    float acc[8] = {0.f,0.f,0.f,0.f,0.f,0.f,0.f,0.f};

    for (int kc = 0; kc < DDIM; kc += 64) {
        #pragma unroll
        for (int i = 0; i < 2; i++) {
            int idx = tid + i * 256;
            int row = idx >> 4, c4 = idx & 15;
            *reinterpret_cast<float4*>(&xs[row][c4 * 4]) =
                *reinterpret_cast<const float4*>(X + (size_t)(t0 + row) * DDIM + kc + c4 * 4);
        }
        #pragma unroll
        for (int i = 0; i < 4; i++) {
            int idx = tid + i * 256;
            int row = idx >> 4, c4 = idx & 15;
            *reinterpret_cast<float4*>(&rws[row][c4 * 4]) =
                *reinterpret_cast<const float4*>(RW + (size_t)row * DDIM + kc + c4 * 4);
        }
        __syncthreads();
        for (int k = 0; k < 64; k++) {
            float xv = xs[t][k];
            #pragma unroll
            for (int j = 0; j < 8; j++) acc[j] += xv * rws[el + 8 * j][k];
        }
        __syncthreads();
    }

    float mx = acc[0];
    #pragma unroll
    for (int j = 1; j < 8; j++) mx = fmaxf(mx, acc[j]);
    #pragma unroll
    for (int m = 1; m < 8; m <<= 1) mx = fmaxf(mx, __shfl_xor_sync(0xffffffffu, mx, m));
    float p[8], s = 0.f;
    #pragma unroll
    for (int j = 0; j < 8; j++) { p[j] = expf(acc[j] - mx); s += p[j]; }
    #pragma unroll
    for (int m = 1; m < 8; m <<= 1) s += __shfl_xor_sync(0xffffffffu, s, m);
    float inv = 1.f / s;
    #pragma unroll
    for (int j = 0; j < 8; j++) probs[t][el + 8 * j] = p[j] * inv;
    __syncthreads();

    if (tid < 32) {
        const int token = t0 + tid;
        float tw[TOPK]; int te[TOPK];
        float psum = 0.f;
        #pragma unroll
        for (int k = 0; k < TOPK; k++) {
            float best = -1.f; int be = 0;
            for (int e2 = 0; e2 < NEXP; e2++) {
                float v = probs[tid][e2];
                if (v > best) { best = v; be = e2; }
            }
            probs[tid][be] = -2.f;
            tw[k] = best; te[k] = be; psum += best;
        }
        float invp = 1.f / psum;
        #pragma unroll
        for (int k = 0; k < TOPK; k++) {
            int pos = atomicAdd(&g_cnt[te[k]], 1);
            if (pos < CAP) {
                g_slot_tok[te[k] * CAP + pos] = token;
                g_slot_w[te[k] * CAP + pos]   = tw[k] * invp;
            }
        }
    }
}

// smem word layouts (uint32 words):
//   A  [m][k2]  stride 36 : 128 rows x (32 k-pairs + 4 pad) = 4608 words (K=64 fp16)
//   B  [k2][n]  stride 136: 32 k-pair rows x (128 n + 8 pad) = 4352 words
// fragment banks: A -> (4g+tig) all distinct; B -> (8tig+g) all distinct.

// ==================== fused gate/up GEMM + SiLU (fp16 mma) ====================
// BM=128, BN=128, BK=64, 512 threads (16 warps 4x4, 32x32 warp tile).
// buffer = A 4608 + Bg 4352 + Bu 4352 = 13312 words; x2 = 104 KB.
template<bool EXPERT>
__global__ __launch_bounds__(512)
void gateup_kernel(const float* __restrict__ X, const float* __restrict__ WG,
                   const float* __restrict__ WU, int ldb) {
    extern __shared__ uint32_t smem[];
    uint32_t* bufs = smem;
    int* s_tok = (int*)(smem + 2 * 13312);

    const int tid = threadIdx.x;
    const int e  = EXPERT ? blockIdx.z : 0;
    const int ne = EXPERT ? min(g_cnt[e], CAP) : T_TOK;
    const int m0 = blockIdx.y * 128;
    if (m0 >= ne) return;
    const int n0 = blockIdx.x * 128;

    const float* Bg = EXPERT ? (WG + (size_t)e * DDIM * FDIM) : WG;
    const float* Bu = EXPERT ? (WU + (size_t)e * DDIM * FDIM) : WU;

    if (EXPERT) {
        for (int i = tid; i < 128; i += 512) {
            int m = m0 + i;
            s_tok[i] = (m < ne) ? g_slot_tok[e * CAP + m] : 0;
        }
        __syncthreads();
    }

    // A producer: unit idx = tid + i*512 -> m = idx>>3, s = idx&7 (8-k span)
    const float* rpA[2];
    int am[2], as_[2];
    #pragma unroll
    for (int i = 0; i < 2; i++) {
        int idx = tid + i * 512;
        am[i] = idx >> 3; as_[i] = idx & 7;
        rpA[i] = (EXPERT ? (X + (size_t)s_tok[am[i]] * DDIM)
                         : (X + (size_t)(m0 + am[i]) * DDIM)) + as_[i] * 8;
    }
    // B producer: unit idx -> kp = idx>>5 (k-pair row), ng = idx&31 (4-n group)
    int bkp[2], bo[2], bw_[2];
    #pragma unroll
    for (int i = 0; i < 2; i++) {
        int idx = tid + i * 512;
        bkp[i] = idx >> 5;
        bo[i]  = n0 + (idx & 31) * 4;
        bw_[i] = bkp[i] * 136 + (idx & 31) * 4;
    }

    const int lane = tid & 31, warp = tid >> 5;
    const int wm = (warp >> 2) * 32, wn = (warp & 3) * 32;
    const int g = lane >> 2, tig = lane & 3;

    float cG[2][4][4] = {};
    float cU[2][4][4] = {};

    float4 hA[4], hg0, hg1, hu0, hu1;

    // ---- prologue: full tile 0 ----
    {
        uint32_t* sA  = bufs;
        uint32_t* sBg = sA + 4608;
        uint32_t* sBu = sBg + 4352;
        #pragma unroll
        for (int i = 0; i < 2; i++) {
            float4 v0 = *reinterpret_cast<const float4*>(rpA[i]);
            float4 v1 = *reinterpret_cast<const float4*>(rpA[i] + 4);
            uint4 w = { pack_h2(v0.x, v0.y), pack_h2(v0.z, v0.w),
                        pack_h2(v1.x, v1.y), pack_h2(v1.z, v1.w) };
            *reinterpret_cast<uint4*>(sA + am[i] * 36 + as_[i] * 4) = w;
        }
        #pragma unroll
        for (int i = 0; i < 2; i++) {
            const float* pg = Bg + (size_t)(2 * bkp[i]) * ldb + bo[i];
            const float* pu = Bu + (size_t)(2 * bkp[i]) * ldb + bo[i];
            float4 r0 = *reinterpret_cast<const float4*>(pg);
            float4 r1 = *reinterpret_cast<const float4*>(pg + ldb);
            uint4 wg = { pack_h2(r0.x, r1.x), pack_h2(r0.y, r1.y),
                         pack_h2(r0.z, r1.z), pack_h2(r0.w, r1.w) };
            *reinterpret_cast<uint4*>(sBg + bw_[i]) = wg;
            float4 u0 = *reinterpret_cast<const float4*>(pu);
            float4 u1 = *reinterpret_cast<const float4*>(pu + ldb);
            uint4 wu = { pack_h2(u0.x, u1.x), pack_h2(u0.y, u1.y),
                         pack_h2(u0.z, u1.z), pack_h2(u0.w, u1.w) };
            *reinterpret_cast<uint4*>(sBu + bw_[i]) = wu;
        }
    }
    __syncthreads();

    const int NK = DDIM / 64;
    for (int kt = 0; kt < NK; kt++) {
        const bool more = (kt + 1 < NK);
        const int k1 = (kt + 1) * 64;
        const uint32_t* uA  = bufs + (kt & 1) * 13312;
        const uint32_t* uBg = uA + 4608;
        const uint32_t* uBu = uBg + 4352;
        uint32_t* nA  = bufs + ((kt + 1) & 1) * 13312;
        uint32_t* nBg = nA + 4608;
        uint32_t* nBu = nBg + 4352;

        // prefetch A (both units) + B unit 0 of next tile
        if (more) {
            #pragma unroll
            for (int i = 0; i < 2; i++) {
                hA[2 * i]     = *reinterpret_cast<const float4*>(rpA[i] + k1);
                hA[2 * i + 1] = *reinterpret_cast<const float4*>(rpA[i] + k1 + 4);
            }
            const float* pg = Bg + (size_t)(k1 + 2 * bkp[0]) * ldb + bo[0];
            const float* pu = Bu + (size_t)(k1 + 2 * bkp[0]) * ldb + bo[0];
            hg0 = *reinterpret_cast<const float4*>(pg);
            hg1 = *reinterpret_cast<const float4*>(pg + ldb);
            hu0 = *reinterpret_cast<const float4*>(pu);
            hu1 = *reinterpret_cast<const float4*>(pu + ldb);
        }

        // compute ks = 0,1  (k 0..31 of this tile)
        #pragma unroll
        for (int ks = 0; ks < 2; ks++) {
            int ko = ks * 8;
            uint32_t a[2][4];
            #pragma unroll
            for (int mf = 0; mf < 2; mf++) {
                int r = wm + mf * 16 + g;
                a[mf][0] = uA[r * 36 + ko + tig];
                a[mf][1] = uA[(r + 8) * 36 + ko + tig];
                a[mf][2] = uA[r * 36 + ko + tig + 4];
                a[mf][3] = uA[(r + 8) * 36 + ko + tig + 4];
            }
            #pragma unroll
            for (int nf = 0; nf < 4; nf++) {
                int cn = wn + nf * 8 + g;
                uint32_t bg0 = uBg[(ko + tig) * 136 + cn];
                uint32_t bg1 = uBg[(ko + tig + 4) * 136 + cn];
                uint32_t bu0 = uBu[(ko + tig) * 136 + cn];
                uint32_t bu1 = uBu[(ko + tig + 4) * 136 + cn];
                mma16(cG[0][nf], a[0], bg0, bg1);
                mma16(cG[1][nf], a[1], bg0, bg1);
                mma16(cU[0][nf], a[0], bu0, bu1);
                mma16(cU[1][nf], a[1], bu0, bu1);
            }
        }

        // store A + B unit0; prefetch B unit1
        if (more) {
            #pragma unroll
            for (int i = 0; i < 2; i++) {
                uint4 w = { pack_h2(hA[2*i].x, hA[2*i].y), pack_h2(hA[2*i].z, hA[2*i].w),
                            pack_h2(hA[2*i+1].x, hA[2*i+1].y), pack_h2(hA[2*i+1].z, hA[2*i+1].w) };
                *reinterpret_cast<uint4*>(nA + am[i] * 36 + as_[i] * 4) = w;
            }
            {
                uint4 wg = { pack_h2(hg0.x, hg1.x), pack_h2(hg0.y, hg1.y),
                             pack_h2(hg0.z, hg1.z), pack_h2(hg0.w, hg1.w) };
                *reinterpret_cast<uint4*>(nBg + bw_[0]) = wg;
                uint4 wu = { pack_h2(hu0.x, hu1.x), pack_h2(hu0.y, hu1.y),
                             pack_h2(hu0.z, hu1.z), pack_h2(hu0.w, hu1.w) };
                *reinterpret_cast<uint4*>(nBu + bw_[0]) = wu;
            }
            const float* pg = Bg + (size_t)(k1 + 2 * bkp[1]) * ldb + bo[1];
            const float* pu = Bu + (size_t)(k1 + 2 * bkp[1]) * ldb + bo[1];
            hg0 = *reinterpret_cast<const float4*>(pg);
            hg1 = *reinterpret_cast<const float4*>(pg + ldb);
            hu0 = *reinterpret_cast<const float4*>(pu);
            hu1 = *reinterpret_cast<const float4*>(pu + ldb);
        }

        // compute ks = 2,3  (k 32..63 of this tile)
        #pragma unroll
        for (int ks = 2; ks < 4; ks++) {
            int ko = ks * 8;
            uint32_t a[2][4];
            #pragma unroll
            for (int mf = 0; mf < 2; mf++) {
                int r = wm + mf * 16 + g;
                a[mf][0] = uA[r * 36 + ko + tig];
                a[mf][1] = uA[(r + 8) * 36 + ko + tig];
                a[mf][2] = uA[r * 36 + ko + tig + 4];
                a[mf][3] = uA[(r + 8) * 36 + ko + tig + 4];
            }
            #pragma unroll
            for (int nf = 0; nf < 4; nf++) {
                int cn = wn + nf * 8 + g;
                uint32_t bg0 = uBg[(ko + tig) * 136 + cn];
                uint32_t bg1 = uBg[(ko + tig + 4) * 136 + cn];
                uint32_t bu0 = uBu[(ko + tig) * 136 + cn];
                uint32_t bu1 = uBu[(ko + tig + 4) * 136 + cn];
                mma16(cG[0][nf], a[0], bg0, bg1);
                mma16(cG[1][nf], a[1], bg0, bg1);
                mma16(cU[0][nf], a[0], bu0, bu1);
                mma16(cU[1][nf], a[1], bu0, bu1);
            }
        }

        // store B unit1
        if (more) {
            uint4 wg = { pack_h2(hg0.x, hg1.x), pack_h2(hg0.y, hg1.y),
                         pack_h2(hg0.z, hg1.z), pack_h2(hg0.w, hg1.w) };
            *reinterpret_cast<uint4*>(nBg + bw_[1]) = wg;
            uint4 wu = { pack_h2(hu0.x, hu1.x), pack_h2(hu0.y, hu1.y),
                         pack_h2(hu0.z, hu1.z), pack_h2(hu0.w, hu1.w) };
            *reinterpret_cast<uint4*>(nBu + bw_[1]) = wu;
        }
        __syncthreads();
    }

    __half* Hbase = EXPERT ? (g_H + (size_t)e * CAP * FDIM) : g_shared_h;
    #pragma unroll
    for (int mf = 0; mf < 2; mf++)
        #pragma unroll
        for (int nf = 0; nf < 4; nf++)
            #pragma unroll
            for (int half_ = 0; half_ < 2; half_++) {
                int row = wm + mf * 16 + g + half_ * 8;
                int col = wn + nf * 8 + 2 * tig;
                int m = m0 + row;
                if (m < ne) {
                    float g0 = cG[mf][nf][half_ * 2],     u0 = cU[mf][nf][half_ * 2];
                    float g1 = cG[mf][nf][half_ * 2 + 1], u1 = cU[mf][nf][half_ * 2 + 1];
                    float h0 = g0 / (1.f + expf(-g0)) * u0;
                    float h1 = g1 / (1.f + expf(-g1)) * u1;
                    *reinterpret_cast<uint32_t*>(Hbase + (size_t)m * FDIM + n0 + col) =
                        pack_h2(h0, h1);
                }
            }
}

// ==================== down GEMM (fp16 mma) ====================
// BM=128, BN=128, BK=64, 512 threads. K = 768 -> 12 k-tiles.
// buffer = A 4608 + B 4352 = 8960 words; x2 = 70 KB.
template<bool EXPERT>
__global__ __launch_bounds__(512)
void down_kernel(const float* __restrict__ WD, float* __restrict__ out) {
    extern __shared__ uint32_t smem[];
    uint32_t* bufs = smem;
    int* s_tok = (int*)(smem + 2 * 8960);
    float* s_w = (float*)(s_tok + 128);

    const int tid = threadIdx.x;
    const int e  = EXPERT ? blockIdx.z : 0;
    const int ne = EXPERT ? min(g_cnt[e], CAP) : T_TOK;
    const int m0 = blockIdx.y * 128;
    if (m0 >= ne) return;
    const int n0 = blockIdx.x * 128;

    const float* B = EXPERT ? (WD + (size_t)e * FDIM * DDIM) : WD;
    const __half* Abase = EXPERT ? (g_H + (size_t)e * CAP * FDIM) : g_shared_h;

    if (EXPERT) {
        for (int i = tid; i < 128; i += 512) {
            int m = m0 + i;
            s_tok[i] = (m < ne) ? g_slot_tok[e * CAP + m] : 0;
            s_w[i]   = (m < ne) ? g_slot_w[e * CAP + m] : 0.f;
        }
        __syncthreads();
    }

    // A producer (fp16 passthrough): unit -> m = idx>>3, s = idx&7
    const __half* rpA[2];
    int am[2], as_[2];
    #pragma unroll
    for (int i = 0; i < 2; i++) {
        int idx = tid + i * 512;
        am[i] = idx >> 3; as_[i] = idx & 7;
        rpA[i] = Abase + (size_t)(m0 + am[i]) * FDIM + as_[i] * 8;
    }
    int bkp[2], bo[2], bw_[2];
    #pragma unroll
    for (int i = 0; i < 2; i++) {
        int idx = tid + i * 512;
        bkp[i] = idx >> 5;
        bo[i]  = n0 + (idx & 31) * 4;
        bw_[i] = bkp[i] * 136 + (idx & 31) * 4;
    }

    const int lane = tid & 31, warp = tid >> 5;
    const int wm = (warp >> 2) * 32, wn = (warp & 3) * 32;
    const int g = lane >> 2, tig = lane & 3;

    float c[2][4][4] = {};
    uint4 hA[2];
    float4 hb0, hb1;

    // ---- prologue: full tile 0 ----
    {
        uint32_t* sA = bufs;
        uint32_t* sB = sA + 4608;
        #pragma unroll
        for (int i = 0; i < 2; i++) {
            uint4 w = *reinterpret_cast<const uint4*>(rpA[i]);
            *reinterpret_cast<uint4*>(sA + am[i] * 36 + as_[i] * 4) = w;
        }
        #pragma unroll
        for (int i = 0; i < 2; i++) {
            const float* pb = B + (size_t)(2 * bkp[i]) * DDIM + bo[i];
            float4 r0 = *reinterpret_cast<const float4*>(pb);
            float4 r1 = *reinterpret_cast<const float4*>(pb + DDIM);
            uint4 w = { pack_h2(r0.x, r1.x), pack_h2(r0.y, r1.y),
                        pack_h2(r0.z, r1.z), pack_h2(r0.w, r1.w) };
            *reinterpret_cast<uint4*>(sB + bw_[i]) = w;
        }
    }
    __syncthreads();

    const int NK = FDIM / 64;
    for (int kt = 0; kt < NK; kt++) {
        const bool more = (kt + 1 < NK);
        const int k1 = (kt + 1) * 64;
        const uint32_t* uA = bufs + (kt & 1) * 8960;
        const uint32_t* uB = uA + 4608;
        uint32_t* nA = bufs + ((kt + 1) & 1) * 8960;
        uint32_t* nB = nA + 4608;

        if (more) {
            #pragma unroll
            for (int i = 0; i < 2; i++)
                hA[i] = *reinterpret_cast<const uint4*>(rpA[i] + k1);
            const float* pb = B + (size_t)(k1 + 2 * bkp[0]) * DDIM + bo[0];
            hb0 = *reinterpret_cast<const float4*>(pb);
            hb1 = *reinterpret_cast<const float4*>(pb + DDIM);
        }

        #pragma unroll
        for (int ks = 0; ks < 2; ks++) {
            int ko = ks * 8;
            uint32_t a[2][4];
            #pragma unroll
            for (int mf = 0; mf < 2; mf++) {
                int r = wm + mf * 16 + g;
                a[mf][0] = uA[r * 36 + ko + tig];
                a[mf][1] = uA[(r + 8) * 36 + ko + tig];
                a[mf][2] = uA[r * 36 + ko + tig + 4];
                a[mf][3] = uA[(r + 8) * 36 + ko + tig + 4];
            }
            #pragma unroll
            for (int nf = 0; nf < 4; nf++) {
                int cn = wn + nf * 8 + g;
                uint32_t b0 = uB[(ko + tig) * 136 + cn];
                uint32_t b1 = uB[(ko + tig + 4) * 136 + cn];
                mma16(c[0][nf], a[0], b0, b1);
                mma16(c[1][nf], a[1], b0, b1);
            }
        }

        if (more) {
            #pragma unroll
            for (int i = 0; i < 2; i++)
                *reinterpret_cast<uint4*>(nA + am[i] * 36 + as_[i] * 4) = hA[i];
            uint4 w = { pack_h2(hb0.x, hb1.x), pack_h2(hb0.y, hb1.y),
                        pack_h2(hb0.z, hb1.z), pack_h2(hb0.w, hb1.w) };
            *reinterpret_cast<uint4*>(nB + bw_[0]) = w;
            const float* pb = B + (size_t)(k1 + 2 * bkp[1]) * DDIM + bo[1];
            hb0 = *reinterpret_cast<const float4*>(pb);
            hb1 = *reinterpret_cast<const float4*>(pb + DDIM);
        }

        #pragma unroll
        for (int ks = 2; ks < 4; ks++) {
            int ko = ks * 8;
            uint32_t a[2][4];
            #pragma unroll
            for (int mf = 0; mf < 2; mf++) {
                int r = wm + mf * 16 + g;
                a[mf][0] = uA[r * 36 + ko + tig];
                a[mf][1] = uA[(r + 8) * 36 + ko + tig];
                a[mf][2] = uA[r * 36 + ko + tig + 4];
                a[mf][3] = uA[(r + 8) * 36 + ko + tig + 4];
            }
            #pragma unroll
            for (int nf = 0; nf < 4; nf++) {
                int cn = wn + nf * 8 + g;
                uint32_t b0 = uB[(ko + tig) * 136 + cn];
                uint32_t b1 = uB[(ko + tig + 4) * 136 + cn];
                mma16(c[0][nf], a[0], b0, b1);
                mma16(c[1][nf], a[1], b0, b1);
            }
        }

        if (more) {
            uint4 w = { pack_h2(hb0.x, hb1.x), pack_h2(hb0.y, hb1.y),
                        pack_h2(hb0.z, hb1.z), pack_h2(hb0.w, hb1.w) };
            *reinterpret_cast<uint4*>(nB + bw_[1]) = w;
        }
        __syncthreads();
    }

    #pragma unroll
    for (int mf = 0; mf < 2; mf++)
        #pragma unroll
        for (int nf = 0; nf < 4; nf++)
            #pragma unroll
            for (int half_ = 0; half_ < 2; half_++) {
                int row = wm + mf * 16 + g + half_ * 8;
                int col = wn + nf * 8 + 2 * tig;
                int m = m0 + row;
                if (m < ne) {
                    float v0 = c[mf][nf][half_ * 2];
                    float v1 = c[mf][nf][half_ * 2 + 1];
                    if (EXPERT) {
                        float w = s_w[row];
                        float* p = out + (size_t)s_tok[row] * DDIM + n0 + col;
                        asm volatile("red.global.add.v2.f32 [%0], {%1,%2};"
                                     :: "l"(p), "f"(v0 * w), "f"(v1 * w) : "memory");
                    } else {
                        float2* p = (float2*)(out + (size_t)m * DDIM + n0 + col);
                        *p = make_float2(v0, v1);
                    }
                }
            }
}

// -------------------- launch --------------------
extern "C" void kernel_launch(void* const* d_in, const int* in_sizes, int n_in,
                              void* d_out, int out_size) {
    const float* X   = (const float*)d_in[0];   // (B,S,D)
    const float* RW  = (const float*)d_in[1];   // (E,D)
    const float* WG  = (const float*)d_in[2];   // (E,D,F)
    const float* WU  = (const float*)d_in[3];   // (E,D,F)
    const float* WD  = (const float*)d_in[4];   // (E,F,D)
    const float* WSG = (const float*)d_in[5];   // (D, 2*SF)
    const float* WSD = (const float*)d_in[6];   // (SF, D)
    float* out = (float*)d_out;

    const int GUSM = (2 * 13312) * 4 + 128 * 4;   // 106496 + 512 = 107008
    const int DSM  = (2 * 8960) * 4 + 128 * 8;    // 71680 + 1024 = 72704

    cudaFuncSetAttribute(gateup_kernel<false>, cudaFuncAttributeMaxDynamicSharedMemorySize, GUSM);
    cudaFuncSetAttribute(gateup_kernel<true>,  cudaFuncAttributeMaxDynamicSharedMemorySize, GUSM);
    cudaFuncSetAttribute(down_kernel<false>,   cudaFuncAttributeMaxDynamicSharedMemorySize, DSM);
    cudaFuncSetAttribute(down_kernel<true>,    cudaFuncAttributeMaxDynamicSharedMemorySize, DSM);

    zero_cnt_kernel<<<1, 64>>>();
    router_kernel<<<T_TOK / 32, 256>>>(X, RW);

    // shared expert gate/up: gate cols [0,768), up cols [768,1536)
    gateup_kernel<false><<<dim3(FDIM / 128, T_TOK / 128, 1), 512, GUSM>>>(X, WSG, WSG + FDIM, 2 * FDIM);
    // routed experts gate/up
    gateup_kernel<true><<<dim3(FDIM / 128, CAP / 128, NEXP), 512, GUSM>>>(X, WG, WU, FDIM);

    // shared expert down (initializes every element of out)
    down_kernel<false><<<dim3(DDIM / 128, T_TOK / 128, 1), 512, DSM>>>(WSD, out);
    // routed experts down (weighted atomic scatter)
    down_kernel<true><<<dim3(DDIM / 128, CAP / 128, NEXP), 512, DSM>>>(WD, out);
}